// round 12
// baseline (speedup 1.0000x reference)
#include <cuda_runtime.h>

// Problem constants
#define BB 128      // batch
#define TT 1024     // time steps
#define XX 256      // input features
#define HH 512      // hidden
#define G3 1536     // 3*H
#define NCTA 128    // persistent grid for recurrence (co-resident on 148 SMs)
#define ROWS 12     // gate rows per CTA (3 gates x 4 h-cols)
#define JCOLS 4     // h columns per CTA  (128 CTAs * 4 = 512)
#define NGRP 8      // barrier level-1 groups (16 CTAs each)

typedef unsigned long long ull;

// -------- scratch (static device globals; no allocation APIs allowed) --------
__device__ float g_xg[(size_t)TT * G3 * BB];   // [t][gate_row][b]
__device__ float g_h[2][HH * BB];              // double-buffered h, [k][b]
__device__ __align__(128) unsigned g_lvl1[NGRP * 32];  // group counters, 1 line apart
__device__ unsigned g_root;                    // root counter (single line)

// -------- packed f32x2 helpers (Blackwell; PTX-only, ptxas won't auto-fuse) --
__device__ __forceinline__ void ffma2(ull& d, ull a, ull b) {
    asm("fma.rn.f32x2 %0, %1, %2, %0;" : "+l"(d) : "l"(a), "l"(b));
}
__device__ __forceinline__ ull dup2(float v) {
    ull r; asm("mov.b64 %0, {%1, %1};" : "=l"(r) : "f"(v)); return r;
}
__device__ __forceinline__ float2 unpk(ull p) {
    float2 r; asm("mov.b64 {%0, %1}, %2;" : "=f"(r.x), "=f"(r.y) : "l"(p)); return r;
}

// -------- barrier primitives (release/acquire; no full membar) --------------
__device__ __forceinline__ unsigned atom_add_acqrel(unsigned* p, unsigned v) {
    unsigned old;
    asm volatile("atom.add.acq_rel.gpu.u32 %0, [%1], %2;"
                 : "=r"(old) : "l"(p), "r"(v) : "memory");
    return old;
}
__device__ __forceinline__ void red_add_release(unsigned* p, unsigned v) {
    asm volatile("red.add.release.gpu.u32 [%0], %1;" :: "l"(p), "r"(v) : "memory");
}
__device__ __forceinline__ unsigned ld_acquire(const unsigned* p) {
    unsigned v;
    asm volatile("ld.acquire.gpu.u32 %0, [%1];" : "=r"(v) : "l"(p) : "memory");
    return v;
}

// ---------------------------------------------------------------------------
// reset: zero h0 and the barrier counters (runs first on every graph replay)
// ---------------------------------------------------------------------------
__global__ void reset_kernel() {
    int i = blockIdx.x * blockDim.x + threadIdx.x;
    if (i == 0) g_root = 0u;
    if (i < NGRP * 32) g_lvl1[i] = 0u;
    if (i < HH * BB) g_h[0][i] = 0.0f;
}

// ---------------------------------------------------------------------------
// Phase 1: xg[t][g][b] = sum_k x[b][t][k] * W_ih[g][k] + b_ih[g]
// grid (12, 1024), block 256, 128x128 tile, K=256, double-buffered SMEM.
// A stored as duplicated f32x2 pairs; B pairs natural. (Unchanged — stable.)
// ---------------------------------------------------------------------------
__global__ __launch_bounds__(256, 2) void proj_kernel(const float* __restrict__ x,
                                                      const float* __restrict__ Wih,
                                                      const float* __restrict__ bih) {
    __shared__ __align__(16) ull   As2[2][8][128];  // duplicated pairs, 16 KB
    __shared__ __align__(16) float Bs[2][8][128];   // 8 KB

    const int t   = blockIdx.y;
    const int g0  = blockIdx.x * 128;
    const int tid = threadIdx.x;
    const int tx  = tid & 15;   // b tile (16)
    const int ty  = tid >> 4;   // g tile (16)

    const int lrow = tid >> 1;        // 0..127
    const int lk   = (tid & 1) * 4;   // 0 or 4

    const float* aptr = Wih + (size_t)(g0 + lrow) * XX + lk;
    const float* bptr = x   + ((size_t)lrow * TT + t) * XX + lk;

    ull acc2[8][4];
#pragma unroll
    for (int i = 0; i < 8; i++)
#pragma unroll
        for (int j = 0; j < 4; j++) acc2[i][j] = 0ull;

    float4 av = *(const float4*)(aptr);
    float4 bv = *(const float4*)(bptr);
    As2[0][lk + 0][lrow] = dup2(av.x); As2[0][lk + 1][lrow] = dup2(av.y);
    As2[0][lk + 2][lrow] = dup2(av.z); As2[0][lk + 3][lrow] = dup2(av.w);
    Bs[0][lk + 0][lrow] = bv.x; Bs[0][lk + 1][lrow] = bv.y;
    Bs[0][lk + 2][lrow] = bv.z; Bs[0][lk + 3][lrow] = bv.w;
    __syncthreads();

    int buf = 0;
    for (int kc = 0; kc < XX; kc += 8) {
        const bool more = (kc + 8 < XX);
        if (more) {
            av = *(const float4*)(aptr + kc + 8);
            bv = *(const float4*)(bptr + kc + 8);
        }
#pragma unroll
        for (int k = 0; k < 8; k++) {
            ulonglong2 a01 = *(const ulonglong2*)&As2[buf][k][ty * 4];
            ulonglong2 a23 = *(const ulonglong2*)&As2[buf][k][ty * 4 + 2];
            ulonglong2 a45 = *(const ulonglong2*)&As2[buf][k][64 + ty * 4];
            ulonglong2 a67 = *(const ulonglong2*)&As2[buf][k][64 + ty * 4 + 2];
            float4 bl = *(const float4*)&Bs[buf][k][tx * 4];
            float4 bh = *(const float4*)&Bs[buf][k][64 + tx * 4];
            const ull* bpl = (const ull*)&bl;   // 2 natural f32x2 pairs
            const ull* bph = (const ull*)&bh;
            ull ad[8] = {a01.x, a01.y, a23.x, a23.y, a45.x, a45.y, a67.x, a67.y};
#pragma unroll
            for (int i = 0; i < 8; i++) {
                ffma2(acc2[i][0], ad[i], bpl[0]);
                ffma2(acc2[i][1], ad[i], bpl[1]);
                ffma2(acc2[i][2], ad[i], bph[0]);
                ffma2(acc2[i][3], ad[i], bph[1]);
            }
        }
        if (more) {
            const int nb = buf ^ 1;
            As2[nb][lk + 0][lrow] = dup2(av.x); As2[nb][lk + 1][lrow] = dup2(av.y);
            As2[nb][lk + 2][lrow] = dup2(av.z); As2[nb][lk + 3][lrow] = dup2(av.w);
            Bs[nb][lk + 0][lrow] = bv.x; Bs[nb][lk + 1][lrow] = bv.y;
            Bs[nb][lk + 2][lrow] = bv.z; Bs[nb][lk + 3][lrow] = bv.w;
        }
        __syncthreads();
        buf ^= 1;
    }

#pragma unroll
    for (int i = 0; i < 8; i++) {
        const int g = g0 + ((i < 4) ? (ty * 4 + i) : (64 + ty * 4 + (i - 4)));
        const float bias = bih[g];
        float2 p0 = unpk(acc2[i][0]), p1 = unpk(acc2[i][1]);
        float2 p2 = unpk(acc2[i][2]), p3 = unpk(acc2[i][3]);
        float* orow = g_xg + ((size_t)t * G3 + g) * BB;
        *(float4*)(orow + tx * 4)      = make_float4(p0.x + bias, p0.y + bias,
                                                     p1.x + bias, p1.y + bias);
        *(float4*)(orow + 64 + tx * 4) = make_float4(p2.x + bias, p2.y + bias,
                                                     p3.x + bias, p3.y + bias);
    }
}

// ---------------------------------------------------------------------------
// Phase 2: persistent GRU recurrence. CHAMPION (R3) compute partition:
// 16 warps = 2 row-groups(6 rows) x 8 k-slices(64); bq = lane*4 (16B h loads);
// acc[6][2] = 24 regs; 6 broadcast LDS.128 per k-pair (half the LDS pressure
// of the kw x bhalf partition — crossbar floor 3072 cyc, under the 6144-cyc
// FFMA2 pipe floor). W_hh dup-paired in SMEM; h in [k][b] layout.
// NEW vs champion: two-level release/acquire barrier with ONE spinner per CTA
// (no 128-way atomic serialize, no 512x threadfence), register-resident hval,
// and next-step xg prefetched before the barrier.
// ---------------------------------------------------------------------------
__global__ __launch_bounds__(512, 1) void gru_kernel(const float* __restrict__ Whh,
                                                     const float* __restrict__ bhh,
                                                     float* __restrict__ out) {
    extern __shared__ __align__(16) char smem_raw[];
    ull*   Wsd = (ull*)smem_raw;                          // [ROWS][HH] dup pairs, 48 KB
    float* red = (float*)(smem_raw + ROWS * HH * 8);      // [2*8][6][BB], 48 KB

    const int c    = blockIdx.x;
    const int j0   = c * JCOLS;
    const int tid  = threadIdx.x;
    const int grpc = c >> 4;                 // barrier group (8 groups of 16 CTAs)

    // load + duplicate this CTA's 12 W_hh rows (row rr = gate*4 + js)
    for (int idx = tid; idx < ROWS * HH; idx += 512) {
        const int rr = idx >> 9;          // /HH
        const int k  = idx & (HH - 1);
        const int grow = (rr >> 2) * HH + j0 + (rr & 3);
        Wsd[rr * HH + k] = dup2(Whh[(size_t)grow * HH + k]);
    }
    __syncthreads();

    const int warp = tid >> 5;
    const int lane = tid & 31;
    const int grp  = warp >> 3;      // row group: rows [grp*6, grp*6+6)
    const int kw   = warp & 7;       // k slice (64 wide)
    const int k0   = kw * 64;
    const int bq   = lane * 4;       // 4 consecutive batch elements

    // epilogue identity: thread owns (b=eb, j=j0+js) forever
    const int eb = tid & 127;
    const int js = tid >> 7;         // 0..3
    float bh[3];
    const float* rp[3];
#pragma unroll
    for (int gate = 0; gate < 3; gate++) {
        bh[gate] = bhh[gate * HH + j0 + js];
        const int rr = gate * 4 + js;
        const int g2 = rr / 6, lr = rr - g2 * 6;
        rp[gate] = &red[((size_t)(g2 * 8) * 6 + lr) * BB + eb];
    }
    float hval = 0.0f;               // own h element, register-resident

    // xg offsets for this thread (constant across t)
    const size_t xo_r = (size_t)(j0 + js) * BB + eb;
    const size_t xo_z = (size_t)(HH + j0 + js) * BB + eb;
    const size_t xo_n = (size_t)(2 * HH + j0 + js) * BB + eb;

    // prefetch xg for t=0
    float xr = __ldcg(g_xg + xo_r);
    float xz = __ldcg(g_xg + xo_z);
    float xn = __ldcg(g_xg + xo_n);

    for (int t = 0; t < TT; t++) {
        const int p = t & 1;
        const float* __restrict__ hc = g_h[p];

        // ---- packed MMA: 6 rows x 64 k x 4 b per thread (768 FFMA2, 24 acc regs)
        ull acc[6][2];
#pragma unroll
        for (int r = 0; r < 6; r++) { acc[r][0] = 0ull; acc[r][1] = 0ull; }

        const ull* wbase = Wsd + (size_t)(grp * 6) * HH + k0;
#pragma unroll 4
        for (int k = 0; k < 64; k += 2) {
            const double2 h0d = __ldcg((const double2*)(hc + (size_t)(k0 + k) * BB + bq));
            const double2 h1d = __ldcg((const double2*)(hc + (size_t)(k0 + k + 1) * BB + bq));
            const ull h0a = (ull)__double_as_longlong(h0d.x);
            const ull h0b = (ull)__double_as_longlong(h0d.y);
            const ull h1a = (ull)__double_as_longlong(h1d.x);
            const ull h1b = (ull)__double_as_longlong(h1d.y);
#pragma unroll
            for (int r = 0; r < 6; r++) {
                const ulonglong2 w = *(const ulonglong2*)(wbase + (size_t)r * HH + k);
                ffma2(acc[r][0], w.x, h0a);
                ffma2(acc[r][1], w.x, h0b);
                ffma2(acc[r][0], w.y, h1a);
                ffma2(acc[r][1], w.y, h1b);
            }
        }

        // partials -> SMEM  (red[(grp*8+kw)][r][bq..bq+3]; 16B stores, conflict-free)
#pragma unroll
        for (int r = 0; r < 6; r++) {
            float2 q0 = unpk(acc[r][0]), q1 = unpk(acc[r][1]);
            *(float4*)&red[((size_t)(grp * 8 + kw) * 6 + r) * BB + bq] =
                make_float4(q0.x, q0.y, q1.x, q1.y);
        }
        __syncthreads();

        // ---- epilogue: reduce 8 k-slices, gates, h update (register h)
        float hg[3];
#pragma unroll
        for (int gate = 0; gate < 3; gate++) {
            const float* q = rp[gate];
            float s0 = q[0];
            float s1 = q[(size_t)1 * 6 * BB];
#pragma unroll
            for (int w = 2; w < 8; w += 2) {
                s0 += q[(size_t)w * 6 * BB];
                s1 += q[(size_t)(w + 1) * 6 * BB];
            }
            hg[gate] = s0 + s1 + bh[gate];
        }
        const float rg = 1.0f / (1.0f + __expf(-(xr + hg[0])));
        const float zg = 1.0f / (1.0f + __expf(-(xz + hg[1])));
        const float ng = tanhf(xn + rg * hg[2]);
        hval = (1.0f - zg) * ng + zg * hval;
        g_h[p ^ 1][(size_t)(j0 + js) * BB + eb] = hval;
        if (t == TT - 1) out[(size_t)eb * HH + (j0 + js)] = hval;  // [B,H]

        // prefetch next step's xg BEFORE the barrier: latency hides in the wait
        const size_t xbase = (size_t)((t + 1 < TT) ? (t + 1) : t) * G3 * BB;
        xr = __ldcg(g_xg + xbase + xo_r);
        xz = __ldcg(g_xg + xbase + xo_z);
        xn = __ldcg(g_xg + xbase + xo_n);

        // ---- two-level grid barrier, one spinner per CTA, release/acquire.
        // bar.sync orders all threads' h stores before tid0's release-atomic
        // (morally strong chain); acquire on root + bar.sync distributes.
        __syncthreads();
        if (tid == 0) {
            const unsigned prev = atom_add_acqrel(&g_lvl1[grpc * 32], 1u);
            if (prev == (unsigned)(t + 1) * 16u - 1u) {
                red_add_release(&g_root, 1u);          // last of this group
            }
            const unsigned target = (unsigned)(t + 1) * (unsigned)NGRP;
            while (ld_acquire(&g_root) < target) { }   // 128 pollers, one line
        }
        __syncthreads();
    }
}

// ---------------------------------------------------------------------------
extern "C" void kernel_launch(void* const* d_in, const int* in_sizes, int n_in,
                              void* d_out, int out_size) {
    const float* x   = (const float*)d_in[0];  // [128,1024,256]
    const float* Wih = (const float*)d_in[1];  // [1536,256]
    const float* Whh = (const float*)d_in[2];  // [1536,512]
    const float* bih = (const float*)d_in[3];  // [1536]
    const float* bhh = (const float*)d_in[4];  // [1536]
    float* out = (float*)d_out;                // [128,512]

    const int gru_smem = ROWS * HH * 8 + 16 * 6 * BB * 4;  // 48KB + 48KB = 96 KB
    cudaFuncSetAttribute(gru_kernel, cudaFuncAttributeMaxDynamicSharedMemorySize,
                         gru_smem);

    reset_kernel<<<(HH * BB + 255) / 256, 256>>>();
    proj_kernel<<<dim3(12, TT), 256>>>(x, Wih, bih);
    gru_kernel<<<NCTA, 512, gru_smem>>>(Whh, bhh, out);
}

// round 14
// speedup vs baseline: 1.0217x; 1.0217x over previous
#include <cuda_runtime.h>

// Problem constants
#define BB 128      // batch
#define TT 1024     // time steps
#define XX 256      // input features
#define HH 512      // hidden
#define G3 1536     // 3*H
#define NCTA 128    // persistent grid for recurrence (co-resident on 148 SMs)
#define ROWS 12     // gate rows per CTA (3 gates x 4 h-cols)
#define JCOLS 4     // h columns per CTA  (128 CTAs * 4 = 512)

typedef unsigned long long ull;

// -------- scratch (static device globals; no allocation APIs allowed) --------
__device__ float g_xg[(size_t)TT * G3 * BB];   // [t][gate_row][b]
__device__ float g_h[2][HH * BB];              // double-buffered h, [k][b]
__device__ unsigned g_bar;                     // single barrier counter

// -------- packed f32x2 helpers (Blackwell; PTX-only, ptxas won't auto-fuse) --
__device__ __forceinline__ void ffma2(ull& d, ull a, ull b) {
    asm("fma.rn.f32x2 %0, %1, %2, %0;" : "+l"(d) : "l"(a), "l"(b));
}
__device__ __forceinline__ ull dup2(float v) {
    ull r; asm("mov.b64 %0, {%1, %1};" : "=l"(r) : "f"(v)); return r;
}
__device__ __forceinline__ float2 unpk(ull p) {
    float2 r; asm("mov.b64 {%0, %1}, %2;" : "=f"(r.x), "=f"(r.y) : "l"(p)); return r;
}

// -------- barrier primitives ------------------------------------------------
__device__ __forceinline__ unsigned atom_add_acqrel(unsigned* p, unsigned v) {
    unsigned old;
    asm volatile("atom.add.acq_rel.gpu.u32 %0, [%1], %2;"
                 : "=r"(old) : "l"(p), "r"(v) : "memory");
    return old;
}
__device__ __forceinline__ unsigned ld_acquire(const unsigned* p) {
    unsigned v;
    asm volatile("ld.acquire.gpu.u32 %0, [%1];" : "=r"(v) : "l"(p) : "memory");
    return v;
}

// ---------------------------------------------------------------------------
// reset: zero h0 and the barrier counter (runs first on every graph replay)
// ---------------------------------------------------------------------------
__global__ void reset_kernel() {
    int i = blockIdx.x * blockDim.x + threadIdx.x;
    if (i == 0) g_bar = 0u;
    if (i < HH * BB) g_h[0][i] = 0.0f;
}

// ---------------------------------------------------------------------------
// Phase 1: xg[t][g][b] = sum_k x[b][t][k] * W_ih[g][k] + b_ih[g]
// grid (12, 1024), block 256, 128x128 tile, K=256, double-buffered SMEM.
// (Unchanged — stable and near model.)
// ---------------------------------------------------------------------------
__global__ __launch_bounds__(256, 2) void proj_kernel(const float* __restrict__ x,
                                                      const float* __restrict__ Wih,
                                                      const float* __restrict__ bih) {
    __shared__ __align__(16) ull   As2[2][8][128];  // duplicated pairs, 16 KB
    __shared__ __align__(16) float Bs[2][8][128];   // 8 KB

    const int t   = blockIdx.y;
    const int g0  = blockIdx.x * 128;
    const int tid = threadIdx.x;
    const int tx  = tid & 15;   // b tile (16)
    const int ty  = tid >> 4;   // g tile (16)

    const int lrow = tid >> 1;        // 0..127
    const int lk   = (tid & 1) * 4;   // 0 or 4

    const float* aptr = Wih + (size_t)(g0 + lrow) * XX + lk;
    const float* bptr = x   + ((size_t)lrow * TT + t) * XX + lk;

    ull acc2[8][4];
#pragma unroll
    for (int i = 0; i < 8; i++)
#pragma unroll
        for (int j = 0; j < 4; j++) acc2[i][j] = 0ull;

    float4 av = *(const float4*)(aptr);
    float4 bv = *(const float4*)(bptr);
    As2[0][lk + 0][lrow] = dup2(av.x); As2[0][lk + 1][lrow] = dup2(av.y);
    As2[0][lk + 2][lrow] = dup2(av.z); As2[0][lk + 3][lrow] = dup2(av.w);
    Bs[0][lk + 0][lrow] = bv.x; Bs[0][lk + 1][lrow] = bv.y;
    Bs[0][lk + 2][lrow] = bv.z; Bs[0][lk + 3][lrow] = bv.w;
    __syncthreads();

    int buf = 0;
    for (int kc = 0; kc < XX; kc += 8) {
        const bool more = (kc + 8 < XX);
        if (more) {
            av = *(const float4*)(aptr + kc + 8);
            bv = *(const float4*)(bptr + kc + 8);
        }
#pragma unroll
        for (int k = 0; k < 8; k++) {
            ulonglong2 a01 = *(const ulonglong2*)&As2[buf][k][ty * 4];
            ulonglong2 a23 = *(const ulonglong2*)&As2[buf][k][ty * 4 + 2];
            ulonglong2 a45 = *(const ulonglong2*)&As2[buf][k][64 + ty * 4];
            ulonglong2 a67 = *(const ulonglong2*)&As2[buf][k][64 + ty * 4 + 2];
            float4 bl = *(const float4*)&Bs[buf][k][tx * 4];
            float4 bh = *(const float4*)&Bs[buf][k][64 + tx * 4];
            const ull* bpl = (const ull*)&bl;   // 2 natural f32x2 pairs
            const ull* bph = (const ull*)&bh;
            ull ad[8] = {a01.x, a01.y, a23.x, a23.y, a45.x, a45.y, a67.x, a67.y};
#pragma unroll
            for (int i = 0; i < 8; i++) {
                ffma2(acc2[i][0], ad[i], bpl[0]);
                ffma2(acc2[i][1], ad[i], bpl[1]);
                ffma2(acc2[i][2], ad[i], bph[0]);
                ffma2(acc2[i][3], ad[i], bph[1]);
            }
        }
        if (more) {
            const int nb = buf ^ 1;
            As2[nb][lk + 0][lrow] = dup2(av.x); As2[nb][lk + 1][lrow] = dup2(av.y);
            As2[nb][lk + 2][lrow] = dup2(av.z); As2[nb][lk + 3][lrow] = dup2(av.w);
            Bs[nb][lk + 0][lrow] = bv.x; Bs[nb][lk + 1][lrow] = bv.y;
            Bs[nb][lk + 2][lrow] = bv.z; Bs[nb][lk + 3][lrow] = bv.w;
        }
        __syncthreads();
        buf ^= 1;
    }

#pragma unroll
    for (int i = 0; i < 8; i++) {
        const int g = g0 + ((i < 4) ? (ty * 4 + i) : (64 + ty * 4 + (i - 4)));
        const float bias = bih[g];
        float2 p0 = unpk(acc2[i][0]), p1 = unpk(acc2[i][1]);
        float2 p2 = unpk(acc2[i][2]), p3 = unpk(acc2[i][3]);
        float* orow = g_xg + ((size_t)t * G3 + g) * BB;
        *(float4*)(orow + tx * 4)      = make_float4(p0.x + bias, p0.y + bias,
                                                     p1.x + bias, p1.y + bias);
        *(float4*)(orow + 64 + tx * 4) = make_float4(p2.x + bias, p2.y + bias,
                                                     p3.x + bias, p3.y + bias);
    }
}

// ---------------------------------------------------------------------------
// Phase 2: persistent GRU recurrence. Champion (R3) compute partition:
// 16 warps = 2 row-groups(6 rows) x 8 k-slices(64); 16B h loads; acc[6][2].
// h loads are L1-CACHED (plain ld) — warps (kw) and (kw+8) stream the same
// 32KB h slice on the same SMSP, so the 2nd reader hits L1 and chip L2
// traffic halves (64 -> 32 MB/step). Cross-step L1 staleness is killed by
// tid0's __threadfence() (gpu scope => CCTL.IVALL, whole-SM L1D invalidate)
// executed after the barrier-wait, before the post-barrier bar.sync.
// Barrier: single monotonic acq_rel counter, one arrival + one spinner per
// CTA (500-800 cyc; the two-level version's chained RTTs were slower).
// ---------------------------------------------------------------------------
__global__ __launch_bounds__(512, 1) void gru_kernel(const float* __restrict__ Whh,
                                                     const float* __restrict__ bhh,
                                                     float* __restrict__ out) {
    extern __shared__ __align__(16) char smem_raw[];
    ull*   Wsd = (ull*)smem_raw;                          // [ROWS][HH] dup pairs, 48 KB
    float* red = (float*)(smem_raw + ROWS * HH * 8);      // [16][6][BB], 48 KB

    const int c   = blockIdx.x;
    const int j0  = c * JCOLS;
    const int tid = threadIdx.x;

    // load + duplicate this CTA's 12 W_hh rows (row rr = gate*4 + js)
    for (int idx = tid; idx < ROWS * HH; idx += 512) {
        const int rr = idx >> 9;          // /HH
        const int k  = idx & (HH - 1);
        const int grow = (rr >> 2) * HH + j0 + (rr & 3);
        Wsd[rr * HH + k] = dup2(Whh[(size_t)grow * HH + k]);
    }
    __syncthreads();

    const int warp = tid >> 5;
    const int lane = tid & 31;
    const int grp  = warp >> 3;      // row group: rows [grp*6, grp*6+6)
    const int kw   = warp & 7;       // k slice (64 wide)
    const int k0   = kw * 64;
    const int bq   = lane * 4;       // 4 consecutive batch elements

    // epilogue identity: thread owns (b=eb, j=j0+js) forever
    const int eb = tid & 127;
    const int js = tid >> 7;         // 0..3
    float bh[3];
    const float* rp[3];
#pragma unroll
    for (int gate = 0; gate < 3; gate++) {
        bh[gate] = bhh[gate * HH + j0 + js];
        const int rr = gate * 4 + js;
        const int g2 = rr / 6, lr = rr - g2 * 6;
        rp[gate] = &red[((size_t)(g2 * 8) * 6 + lr) * BB + eb];
    }
    float hval = 0.0f;               // own h element, register-resident

    // xg offsets for this thread (constant across t)
    const size_t xo_r = (size_t)(j0 + js) * BB + eb;
    const size_t xo_z = (size_t)(HH + j0 + js) * BB + eb;
    const size_t xo_n = (size_t)(2 * HH + j0 + js) * BB + eb;

    // prefetch xg for t=0 (xg is write-once, L1 caching is safe)
    float xr = g_xg[xo_r];
    float xz = g_xg[xo_z];
    float xn = g_xg[xo_n];

    for (int t = 0; t < TT; t++) {
        const int p = t & 1;
        const float* __restrict__ hc = g_h[p];

        // ---- packed MMA: 6 rows x 64 k x 4 b per thread (768 FFMA2, 24 acc regs)
        ull acc[6][2];
#pragma unroll
        for (int r = 0; r < 6; r++) { acc[r][0] = 0ull; acc[r][1] = 0ull; }

        const ull* wbase = Wsd + (size_t)(grp * 6) * HH + k0;
#pragma unroll 4
        for (int k = 0; k < 64; k += 2) {
            // plain (L1-allocating) 16B loads — 2nd row-group warp hits L1
            const double2 h0d = *(const double2*)(hc + (size_t)(k0 + k) * BB + bq);
            const double2 h1d = *(const double2*)(hc + (size_t)(k0 + k + 1) * BB + bq);
            const ull h0a = (ull)__double_as_longlong(h0d.x);
            const ull h0b = (ull)__double_as_longlong(h0d.y);
            const ull h1a = (ull)__double_as_longlong(h1d.x);
            const ull h1b = (ull)__double_as_longlong(h1d.y);
#pragma unroll
            for (int r = 0; r < 6; r++) {
                const ulonglong2 w = *(const ulonglong2*)(wbase + (size_t)r * HH + k);
                ffma2(acc[r][0], w.x, h0a);
                ffma2(acc[r][1], w.x, h0b);
                ffma2(acc[r][0], w.y, h1a);
                ffma2(acc[r][1], w.y, h1b);
            }
        }

        // partials -> SMEM  (red[(grp*8+kw)][r][bq..bq+3]; 16B stores)
#pragma unroll
        for (int r = 0; r < 6; r++) {
            float2 q0 = unpk(acc[r][0]), q1 = unpk(acc[r][1]);
            *(float4*)&red[((size_t)(grp * 8 + kw) * 6 + r) * BB + bq] =
                make_float4(q0.x, q0.y, q1.x, q1.y);
        }
        __syncthreads();

        // ---- epilogue: reduce 16 partials, gates, h update (register h)
        float hg[3];
#pragma unroll
        for (int gate = 0; gate < 3; gate++) {
            const float* q = rp[gate];
            float s0 = q[0];
            float s1 = q[(size_t)1 * 6 * BB];
#pragma unroll
            for (int w = 2; w < 8; w += 2) {
                s0 += q[(size_t)w * 6 * BB];
                s1 += q[(size_t)(w + 1) * 6 * BB];
            }
            hg[gate] = s0 + s1 + bh[gate];
        }
        const float rg = 1.0f / (1.0f + __expf(-(xr + hg[0])));
        const float zg = 1.0f / (1.0f + __expf(-(xz + hg[1])));
        const float ng = tanhf(xn + rg * hg[2]);
        hval = (1.0f - zg) * ng + zg * hval;
        g_h[p ^ 1][(size_t)(j0 + js) * BB + eb] = hval;
        if (t == TT - 1) out[(size_t)eb * HH + (j0 + js)] = hval;  // [B,H]

        // prefetch next step's xg BEFORE the barrier (write-once data; its
        // value is latched into registers before the IVALL below)
        const size_t xbase = (size_t)((t + 1 < TT) ? (t + 1) : t) * G3 * BB;
        xr = __ldcg(g_xg + xbase + xo_r);
        xz = __ldcg(g_xg + xbase + xo_z);
        xn = __ldcg(g_xg + xbase + xo_n);

        // ---- grid barrier: single acq_rel counter, one spinner per CTA.
        // bar.sync orders all threads' h stores before tid0's release-atomic.
        __syncthreads();
        if (tid == 0) {
            atom_add_acqrel(&g_bar, 1u);
            const unsigned target = (unsigned)(t + 1) * (unsigned)NCTA;
            while (ld_acquire(&g_bar) < target) { }
            // gpu-scope fence => CCTL.IVALL: invalidate this SM's L1D so the
            // next step's h reads (L1-cached) cannot see stale lines.
            __threadfence();
        }
        __syncthreads();
    }
}

// ---------------------------------------------------------------------------
extern "C" void kernel_launch(void* const* d_in, const int* in_sizes, int n_in,
                              void* d_out, int out_size) {
    const float* x   = (const float*)d_in[0];  // [128,1024,256]
    const float* Wih = (const float*)d_in[1];  // [1536,256]
    const float* Whh = (const float*)d_in[2];  // [1536,512]
    const float* bih = (const float*)d_in[3];  // [1536]
    const float* bhh = (const float*)d_in[4];  // [1536]
    float* out = (float*)d_out;                // [128,512]

    const int gru_smem = ROWS * HH * 8 + 16 * 6 * BB * 4;  // 48KB + 48KB = 96 KB
    cudaFuncSetAttribute(gru_kernel, cudaFuncAttributeMaxDynamicSharedMemorySize,
                         gru_smem);

    reset_kernel<<<(HH * BB + 255) / 256, 256>>>();
    proj_kernel<<<dim3(12, TT), 256>>>(x, Wih, bih);
    gru_kernel<<<NCTA, 512, gru_smem>>>(Whh, bhh, out);
}

// round 15
// speedup vs baseline: 1.0241x; 1.0023x over previous
#include <cuda_runtime.h>

// Problem constants
#define BB 128      // batch
#define TT 1024     // time steps
#define XX 256      // input features
#define HH 512      // hidden
#define G3 1536     // 3*H
#define NCTA 128    // persistent grid for recurrence (co-resident on 148 SMs)
#define ROWS 12     // gate rows per CTA (3 gates x 4 h-cols)
#define JCOLS 4     // h columns per CTA  (128 CTAs * 4 = 512)

typedef unsigned long long ull;

// -------- scratch (static device globals; no allocation APIs allowed) --------
__device__ float g_xg[(size_t)TT * G3 * BB];   // [t][gate_row][b]
__device__ float g_h[2][HH * BB];              // double-buffered h, [k][b]
__device__ unsigned g_bar;                     // single barrier counter

// -------- packed f32x2 helpers (Blackwell; PTX-only, ptxas won't auto-fuse) --
__device__ __forceinline__ void ffma2(ull& d, ull a, ull b) {
    asm("fma.rn.f32x2 %0, %1, %2, %0;" : "+l"(d) : "l"(a), "l"(b));
}
__device__ __forceinline__ ull dup2(float v) {
    ull r; asm("mov.b64 %0, {%1, %1};" : "=l"(r) : "f"(v)); return r;
}
__device__ __forceinline__ float2 unpk(ull p) {
    float2 r; asm("mov.b64 {%0, %1}, %2;" : "=f"(r.x), "=f"(r.y) : "l"(p)); return r;
}

// -------- barrier primitives ------------------------------------------------
__device__ __forceinline__ unsigned atom_add_acqrel(unsigned* p, unsigned v) {
    unsigned old;
    asm volatile("atom.add.acq_rel.gpu.u32 %0, [%1], %2;"
                 : "=r"(old) : "l"(p), "r"(v) : "memory");
    return old;
}
__device__ __forceinline__ unsigned ld_acquire(const unsigned* p) {
    unsigned v;
    asm volatile("ld.acquire.gpu.u32 %0, [%1];" : "=r"(v) : "l"(p) : "memory");
    return v;
}

// ---------------------------------------------------------------------------
// reset: zero h0 and the barrier counter (runs first on every graph replay)
// ---------------------------------------------------------------------------
__global__ void reset_kernel() {
    int i = blockIdx.x * blockDim.x + threadIdx.x;
    if (i == 0) g_bar = 0u;
    if (i < HH * BB) g_h[0][i] = 0.0f;
}

// ---------------------------------------------------------------------------
// Phase 1: xg[t][g][b] = sum_k x[b][t][k] * W_ih[g][k] + b_ih[g]
// grid (12, 1024), block 256, 128x128 tile, K=256, double-buffered SMEM.
// (Unchanged — stable and near model.)
// ---------------------------------------------------------------------------
__global__ __launch_bounds__(256, 2) void proj_kernel(const float* __restrict__ x,
                                                      const float* __restrict__ Wih,
                                                      const float* __restrict__ bih) {
    __shared__ __align__(16) ull   As2[2][8][128];  // duplicated pairs, 16 KB
    __shared__ __align__(16) float Bs[2][8][128];   // 8 KB

    const int t   = blockIdx.y;
    const int g0  = blockIdx.x * 128;
    const int tid = threadIdx.x;
    const int tx  = tid & 15;   // b tile (16)
    const int ty  = tid >> 4;   // g tile (16)

    const int lrow = tid >> 1;        // 0..127
    const int lk   = (tid & 1) * 4;   // 0 or 4

    const float* aptr = Wih + (size_t)(g0 + lrow) * XX + lk;
    const float* bptr = x   + ((size_t)lrow * TT + t) * XX + lk;

    ull acc2[8][4];
#pragma unroll
    for (int i = 0; i < 8; i++)
#pragma unroll
        for (int j = 0; j < 4; j++) acc2[i][j] = 0ull;

    float4 av = *(const float4*)(aptr);
    float4 bv = *(const float4*)(bptr);
    As2[0][lk + 0][lrow] = dup2(av.x); As2[0][lk + 1][lrow] = dup2(av.y);
    As2[0][lk + 2][lrow] = dup2(av.z); As2[0][lk + 3][lrow] = dup2(av.w);
    Bs[0][lk + 0][lrow] = bv.x; Bs[0][lk + 1][lrow] = bv.y;
    Bs[0][lk + 2][lrow] = bv.z; Bs[0][lk + 3][lrow] = bv.w;
    __syncthreads();

    int buf = 0;
    for (int kc = 0; kc < XX; kc += 8) {
        const bool more = (kc + 8 < XX);
        if (more) {
            av = *(const float4*)(aptr + kc + 8);
            bv = *(const float4*)(bptr + kc + 8);
        }
#pragma unroll
        for (int k = 0; k < 8; k++) {
            ulonglong2 a01 = *(const ulonglong2*)&As2[buf][k][ty * 4];
            ulonglong2 a23 = *(const ulonglong2*)&As2[buf][k][ty * 4 + 2];
            ulonglong2 a45 = *(const ulonglong2*)&As2[buf][k][64 + ty * 4];
            ulonglong2 a67 = *(const ulonglong2*)&As2[buf][k][64 + ty * 4 + 2];
            float4 bl = *(const float4*)&Bs[buf][k][tx * 4];
            float4 bh = *(const float4*)&Bs[buf][k][64 + tx * 4];
            const ull* bpl = (const ull*)&bl;   // 2 natural f32x2 pairs
            const ull* bph = (const ull*)&bh;
            ull ad[8] = {a01.x, a01.y, a23.x, a23.y, a45.x, a45.y, a67.x, a67.y};
#pragma unroll
            for (int i = 0; i < 8; i++) {
                ffma2(acc2[i][0], ad[i], bpl[0]);
                ffma2(acc2[i][1], ad[i], bpl[1]);
                ffma2(acc2[i][2], ad[i], bph[0]);
                ffma2(acc2[i][3], ad[i], bph[1]);
            }
        }
        if (more) {
            const int nb = buf ^ 1;
            As2[nb][lk + 0][lrow] = dup2(av.x); As2[nb][lk + 1][lrow] = dup2(av.y);
            As2[nb][lk + 2][lrow] = dup2(av.z); As2[nb][lk + 3][lrow] = dup2(av.w);
            Bs[nb][lk + 0][lrow] = bv.x; Bs[nb][lk + 1][lrow] = bv.y;
            Bs[nb][lk + 2][lrow] = bv.z; Bs[nb][lk + 3][lrow] = bv.w;
        }
        __syncthreads();
        buf ^= 1;
    }

#pragma unroll
    for (int i = 0; i < 8; i++) {
        const int g = g0 + ((i < 4) ? (ty * 4 + i) : (64 + ty * 4 + (i - 4)));
        const float bias = bih[g];
        float2 p0 = unpk(acc2[i][0]), p1 = unpk(acc2[i][1]);
        float2 p2 = unpk(acc2[i][2]), p3 = unpk(acc2[i][3]);
        float* orow = g_xg + ((size_t)t * G3 + g) * BB;
        *(float4*)(orow + tx * 4)      = make_float4(p0.x + bias, p0.y + bias,
                                                     p1.x + bias, p1.y + bias);
        *(float4*)(orow + 64 + tx * 4) = make_float4(p2.x + bias, p2.y + bias,
                                                     p3.x + bias, p3.y + bias);
    }
}

// ---------------------------------------------------------------------------
// Phase 2: persistent GRU recurrence. Champion (R3) compute partition:
// 16 warps = 2 row-groups(6 rows) x 8 k-slices(64); 16B h loads; acc[6][2].
// h loads are L1-CACHED (plain ld) — warps (kw) and (kw+8) stream the same
// 32KB h slice on the same SMSP, so the 2nd reader hits L1 and chip L2
// traffic halves (64 -> 32 MB/step). Cross-step L1 staleness is killed by
// tid0's __threadfence() (gpu scope => CCTL.IVALL, whole-SM L1D invalidate)
// executed after the barrier-wait, before the post-barrier bar.sync.
// Barrier: single monotonic acq_rel counter, one arrival + one spinner per
// CTA (500-800 cyc; the two-level version's chained RTTs were slower).
// ---------------------------------------------------------------------------
__global__ __launch_bounds__(512, 1) void gru_kernel(const float* __restrict__ Whh,
                                                     const float* __restrict__ bhh,
                                                     float* __restrict__ out) {
    extern __shared__ __align__(16) char smem_raw[];
    ull*   Wsd = (ull*)smem_raw;                          // [ROWS][HH] dup pairs, 48 KB
    float* red = (float*)(smem_raw + ROWS * HH * 8);      // [16][6][BB], 48 KB

    const int c   = blockIdx.x;
    const int j0  = c * JCOLS;
    const int tid = threadIdx.x;

    // load + duplicate this CTA's 12 W_hh rows (row rr = gate*4 + js)
    for (int idx = tid; idx < ROWS * HH; idx += 512) {
        const int rr = idx >> 9;          // /HH
        const int k  = idx & (HH - 1);
        const int grow = (rr >> 2) * HH + j0 + (rr & 3);
        Wsd[rr * HH + k] = dup2(Whh[(size_t)grow * HH + k]);
    }
    __syncthreads();

    const int warp = tid >> 5;
    const int lane = tid & 31;
    const int grp  = warp >> 3;      // row group: rows [grp*6, grp*6+6)
    const int kw   = warp & 7;       // k slice (64 wide)
    const int k0   = kw * 64;
    const int bq   = lane * 4;       // 4 consecutive batch elements

    // epilogue identity: thread owns (b=eb, j=j0+js) forever
    const int eb = tid & 127;
    const int js = tid >> 7;         // 0..3
    float bh[3];
    const float* rp[3];
#pragma unroll
    for (int gate = 0; gate < 3; gate++) {
        bh[gate] = bhh[gate * HH + j0 + js];
        const int rr = gate * 4 + js;
        const int g2 = rr / 6, lr = rr - g2 * 6;
        rp[gate] = &red[((size_t)(g2 * 8) * 6 + lr) * BB + eb];
    }
    float hval = 0.0f;               // own h element, register-resident

    // xg offsets for this thread (constant across t)
    const size_t xo_r = (size_t)(j0 + js) * BB + eb;
    const size_t xo_z = (size_t)(HH + j0 + js) * BB + eb;
    const size_t xo_n = (size_t)(2 * HH + j0 + js) * BB + eb;

    // prefetch xg for t=0 (xg is write-once, L1 caching is safe)
    float xr = g_xg[xo_r];
    float xz = g_xg[xo_z];
    float xn = g_xg[xo_n];

    for (int t = 0; t < TT; t++) {
        const int p = t & 1;
        const float* __restrict__ hc = g_h[p];

        // ---- packed MMA: 6 rows x 64 k x 4 b per thread (768 FFMA2, 24 acc regs)
        ull acc[6][2];
#pragma unroll
        for (int r = 0; r < 6; r++) { acc[r][0] = 0ull; acc[r][1] = 0ull; }

        const ull* wbase = Wsd + (size_t)(grp * 6) * HH + k0;
#pragma unroll 4
        for (int k = 0; k < 64; k += 2) {
            // plain (L1-allocating) 16B loads — 2nd row-group warp hits L1
            const double2 h0d = *(const double2*)(hc + (size_t)(k0 + k) * BB + bq);
            const double2 h1d = *(const double2*)(hc + (size_t)(k0 + k + 1) * BB + bq);
            const ull h0a = (ull)__double_as_longlong(h0d.x);
            const ull h0b = (ull)__double_as_longlong(h0d.y);
            const ull h1a = (ull)__double_as_longlong(h1d.x);
            const ull h1b = (ull)__double_as_longlong(h1d.y);
#pragma unroll
            for (int r = 0; r < 6; r++) {
                const ulonglong2 w = *(const ulonglong2*)(wbase + (size_t)r * HH + k);
                ffma2(acc[r][0], w.x, h0a);
                ffma2(acc[r][1], w.x, h0b);
                ffma2(acc[r][0], w.y, h1a);
                ffma2(acc[r][1], w.y, h1b);
            }
        }

        // partials -> SMEM  (red[(grp*8+kw)][r][bq..bq+3]; 16B stores)
#pragma unroll
        for (int r = 0; r < 6; r++) {
            float2 q0 = unpk(acc[r][0]), q1 = unpk(acc[r][1]);
            *(float4*)&red[((size_t)(grp * 8 + kw) * 6 + r) * BB + bq] =
                make_float4(q0.x, q0.y, q1.x, q1.y);
        }
        __syncthreads();

        // ---- epilogue: reduce 16 partials, gates, h update (register h)
        float hg[3];
#pragma unroll
        for (int gate = 0; gate < 3; gate++) {
            const float* q = rp[gate];
            float s0 = q[0];
            float s1 = q[(size_t)1 * 6 * BB];
#pragma unroll
            for (int w = 2; w < 8; w += 2) {
                s0 += q[(size_t)w * 6 * BB];
                s1 += q[(size_t)(w + 1) * 6 * BB];
            }
            hg[gate] = s0 + s1 + bh[gate];
        }
        const float rg = 1.0f / (1.0f + __expf(-(xr + hg[0])));
        const float zg = 1.0f / (1.0f + __expf(-(xz + hg[1])));
        const float ng = tanhf(xn + rg * hg[2]);
        hval = (1.0f - zg) * ng + zg * hval;
        g_h[p ^ 1][(size_t)(j0 + js) * BB + eb] = hval;
        if (t == TT - 1) out[(size_t)eb * HH + (j0 + js)] = hval;  // [B,H]

        // prefetch next step's xg BEFORE the barrier (write-once data; its
        // value is latched into registers before the IVALL below)
        const size_t xbase = (size_t)((t + 1 < TT) ? (t + 1) : t) * G3 * BB;
        xr = __ldcg(g_xg + xbase + xo_r);
        xz = __ldcg(g_xg + xbase + xo_z);
        xn = __ldcg(g_xg + xbase + xo_n);

        // ---- grid barrier: single acq_rel counter, one spinner per CTA.
        // bar.sync orders all threads' h stores before tid0's release-atomic.
        __syncthreads();
        if (tid == 0) {
            atom_add_acqrel(&g_bar, 1u);
            const unsigned target = (unsigned)(t + 1) * (unsigned)NCTA;
            while (ld_acquire(&g_bar) < target) { }
            // gpu-scope fence => CCTL.IVALL: invalidate this SM's L1D so the
            // next step's h reads (L1-cached) cannot see stale lines.
            __threadfence();
        }
        __syncthreads();
    }
}

// ---------------------------------------------------------------------------
extern "C" void kernel_launch(void* const* d_in, const int* in_sizes, int n_in,
                              void* d_out, int out_size) {
    const float* x   = (const float*)d_in[0];  // [128,1024,256]
    const float* Wih = (const float*)d_in[1];  // [1536,256]
    const float* Whh = (const float*)d_in[2];  // [1536,512]
    const float* bih = (const float*)d_in[3];  // [1536]
    const float* bhh = (const float*)d_in[4];  // [1536]
    float* out = (float*)d_out;                // [128,512]

    const int gru_smem = ROWS * HH * 8 + 16 * 6 * BB * 4;  // 48KB + 48KB = 96 KB
    cudaFuncSetAttribute(gru_kernel, cudaFuncAttributeMaxDynamicSharedMemorySize,
                         gru_smem);

    reset_kernel<<<(HH * BB + 255) / 256, 256>>>();
    proj_kernel<<<dim3(12, TT), 256>>>(x, Wih, bih);
    gru_kernel<<<NCTA, 512, gru_smem>>>(Whh, bhh, out);
}